// round 1
// baseline (speedup 1.0000x reference)
#include <cuda_runtime.h>
#include <math.h>

// Problem constants (fixed shapes from setup_inputs)
#define BSZ 8
#define SRC 512
#define TGT 256
#define HID 1024
#define TV  15000
#define VOC 20000
#define BT  (BSZ*TGT)   // 2048
#define EPSF 1.1920928955078125e-7f
#define NEG_BIG -1000000000.0f

// Scratch (device globals; no allocations allowed)
__device__ float g_Q[BT * HID];          // gelu(feature @ W_q^T + b_q)   8 MB
__device__ float g_att[BT * SRC];        // raw Q.K^T (pre-scale)          4 MB
__device__ float g_pexp[BT * SRC];       // exp(pointer_atten)             4 MB
__device__ float4 g_rowc[BT];            // {gate, c1, c2, t2default}

// ---------------------------------------------------------------------------
// Kernel 1: Q = gelu(feature @ W_q^T + b_q)
// A [2048 x 1024] row-major, B [1024 x 1024] row-major (both K-contiguous).
// Tile 128(M) x 64(N) x 16(K), 256 threads, 8x4 microtile, double-buffered.
// ---------------------------------------------------------------------------
__global__ __launch_bounds__(256, 2) void k_gemm_gelu(
    const float* __restrict__ A, const float* __restrict__ B,
    const float* __restrict__ bias)
{
    __shared__ __align__(16) float As[2][16][132];
    __shared__ __align__(16) float Bs[2][16][68];

    const int tid = threadIdx.x;
    const int m0 = blockIdx.y * 128;
    const int n0 = blockIdx.x * 64;
    const int tx = tid & 15;      // n micro
    const int ty = tid >> 4;      // m micro

    const int am0 = tid >> 2;             // rows 0..63
    const int am1 = am0 + 64;             // rows 64..127
    const int ak4 = (tid & 3) * 4;        // k offset within 16
    const int bn  = tid >> 2;             // B row 0..63

    const float* Ap0 = A + (size_t)(m0 + am0) * HID + ak4;
    const float* Ap1 = A + (size_t)(m0 + am1) * HID + ak4;
    const float* Bp  = B + (size_t)(n0 + bn)  * HID + ak4;

    float4 ra0 = *(const float4*)Ap0;
    float4 ra1 = *(const float4*)Ap1;
    float4 rb  = *(const float4*)Bp;

#define STORE_TILE_1(bf) do { \
    As[bf][ak4+0][am0]=ra0.x; As[bf][ak4+1][am0]=ra0.y; As[bf][ak4+2][am0]=ra0.z; As[bf][ak4+3][am0]=ra0.w; \
    As[bf][ak4+0][am1]=ra1.x; As[bf][ak4+1][am1]=ra1.y; As[bf][ak4+2][am1]=ra1.z; As[bf][ak4+3][am1]=ra1.w; \
    Bs[bf][ak4+0][bn]=rb.x;   Bs[bf][ak4+1][bn]=rb.y;   Bs[bf][ak4+2][bn]=rb.z;   Bs[bf][ak4+3][bn]=rb.w;   \
    } while(0)

    STORE_TILE_1(0);
    __syncthreads();

    float acc[8][4];
#pragma unroll
    for (int i = 0; i < 8; i++)
#pragma unroll
        for (int j = 0; j < 4; j++) acc[i][j] = 0.f;

    const int NK = HID / 16;  // 64
    for (int kc = 0; kc < NK; kc++) {
        const int cur = kc & 1;
        if (kc + 1 < NK) {
            const int ko = (kc + 1) * 16;
            ra0 = *(const float4*)(Ap0 + ko);
            ra1 = *(const float4*)(Ap1 + ko);
            rb  = *(const float4*)(Bp  + ko);
        }
#pragma unroll
        for (int kk = 0; kk < 16; kk++) {
            float4 a0 = *(const float4*)&As[cur][kk][ty * 8];
            float4 a1 = *(const float4*)&As[cur][kk][ty * 8 + 4];
            float4 bb = *(const float4*)&Bs[cur][kk][tx * 4];
            float av[8] = {a0.x,a0.y,a0.z,a0.w,a1.x,a1.y,a1.z,a1.w};
            float bv[4] = {bb.x,bb.y,bb.z,bb.w};
#pragma unroll
            for (int i = 0; i < 8; i++)
#pragma unroll
                for (int j = 0; j < 4; j++)
                    acc[i][j] = fmaf(av[i], bv[j], acc[i][j]);
        }
        if (kc + 1 < NK) {
            const int nxt = cur ^ 1;
            STORE_TILE_1(nxt);
            __syncthreads();
        }
    }

    // Epilogue: bias + exact GELU, vectorized store
    const float4 b4 = *(const float4*)&bias[n0 + tx * 4];
    const float bvv[4] = {b4.x, b4.y, b4.z, b4.w};
#pragma unroll
    for (int i = 0; i < 8; i++) {
        const int row = m0 + ty * 8 + i;
        float o[4];
#pragma unroll
        for (int j = 0; j < 4; j++) {
            float v = acc[i][j] + bvv[j];
            o[j] = 0.5f * v * (1.0f + erff(v * 0.70710678118654752f));
        }
        *(float4*)&g_Q[(size_t)row * HID + n0 + tx * 4] = make_float4(o[0], o[1], o[2], o[3]);
    }
#undef STORE_TILE_1
}

// ---------------------------------------------------------------------------
// Kernel 2: raw attention GEMM per batch: att[b,t,s] = Q[b,t,:].memory[b,s,:]
// (sentinel column s=512 handled in kernel 3; only s<512 here)
// ---------------------------------------------------------------------------
__global__ __launch_bounds__(256, 2) void k_att_gemm(const float* __restrict__ memory)
{
    __shared__ __align__(16) float As[2][16][132];
    __shared__ __align__(16) float Bs[2][16][68];

    const int tid = threadIdx.x;
    const int b  = blockIdx.z;
    const int m0 = blockIdx.y * 128;   // t tile (0 or 128)
    const int n0 = blockIdx.x * 64;    // s tile (0..448)
    const int tx = tid & 15;
    const int ty = tid >> 4;

    const int am0 = tid >> 2;
    const int am1 = am0 + 64;
    const int ak4 = (tid & 3) * 4;
    const int bn  = tid >> 2;

    const float* Ap0 = g_Q + (size_t)(b * TGT + m0 + am0) * HID + ak4;
    const float* Ap1 = g_Q + (size_t)(b * TGT + m0 + am1) * HID + ak4;
    const float* Bp  = memory + ((size_t)b * SRC + n0 + bn) * HID + ak4;

    float4 ra0 = *(const float4*)Ap0;
    float4 ra1 = *(const float4*)Ap1;
    float4 rb  = *(const float4*)Bp;

#define STORE_TILE_2(bf) do { \
    As[bf][ak4+0][am0]=ra0.x; As[bf][ak4+1][am0]=ra0.y; As[bf][ak4+2][am0]=ra0.z; As[bf][ak4+3][am0]=ra0.w; \
    As[bf][ak4+0][am1]=ra1.x; As[bf][ak4+1][am1]=ra1.y; As[bf][ak4+2][am1]=ra1.z; As[bf][ak4+3][am1]=ra1.w; \
    Bs[bf][ak4+0][bn]=rb.x;   Bs[bf][ak4+1][bn]=rb.y;   Bs[bf][ak4+2][bn]=rb.z;   Bs[bf][ak4+3][bn]=rb.w;   \
    } while(0)

    STORE_TILE_2(0);
    __syncthreads();

    float acc[8][4];
#pragma unroll
    for (int i = 0; i < 8; i++)
#pragma unroll
        for (int j = 0; j < 4; j++) acc[i][j] = 0.f;

    const int NK = HID / 16;
    for (int kc = 0; kc < NK; kc++) {
        const int cur = kc & 1;
        if (kc + 1 < NK) {
            const int ko = (kc + 1) * 16;
            ra0 = *(const float4*)(Ap0 + ko);
            ra1 = *(const float4*)(Ap1 + ko);
            rb  = *(const float4*)(Bp  + ko);
        }
#pragma unroll
        for (int kk = 0; kk < 16; kk++) {
            float4 a0 = *(const float4*)&As[cur][kk][ty * 8];
            float4 a1 = *(const float4*)&As[cur][kk][ty * 8 + 4];
            float4 bb = *(const float4*)&Bs[cur][kk][tx * 4];
            float av[8] = {a0.x,a0.y,a0.z,a0.w,a1.x,a1.y,a1.z,a1.w};
            float bv[4] = {bb.x,bb.y,bb.z,bb.w};
#pragma unroll
            for (int i = 0; i < 8; i++)
#pragma unroll
                for (int j = 0; j < 4; j++)
                    acc[i][j] = fmaf(av[i], bv[j], acc[i][j]);
        }
        if (kc + 1 < NK) {
            const int nxt = cur ^ 1;
            STORE_TILE_2(nxt);
            __syncthreads();
        }
    }

#pragma unroll
    for (int i = 0; i < 8; i++) {
        const int row = b * TGT + m0 + ty * 8 + i;
        *(float4*)&g_att[(size_t)row * SRC + n0 + tx * 4] =
            make_float4(acc[i][0], acc[i][1], acc[i][2], acc[i][3]);
    }
#undef STORE_TILE_2
}

// ---------------------------------------------------------------------------
// Kernel 3: per-(b,t) row: sentinel dot, mask, log_softmax over 513,
// store exp(pointer_atten) and row constants.
// ---------------------------------------------------------------------------
__global__ __launch_bounds__(256) void k_softmax_row(
    const float* __restrict__ sentinel, const unsigned char* __restrict__ mask)
{
    const int bt = blockIdx.x;
    const int b = bt / TGT;
    const int tid = threadIdx.x;
    __shared__ float red[256];

    // sentinel dot: Q[bt,:] . sentinel
    {
        const float4 qa = *(const float4*)(g_Q + (size_t)bt * HID + tid * 4);
        const float4 sa = *(const float4*)(sentinel + tid * 4);
        red[tid] = qa.x*sa.x + qa.y*sa.y + qa.z*sa.z + qa.w*sa.w;
    }
    __syncthreads();
    for (int o = 128; o > 0; o >>= 1) {
        if (tid < o) red[tid] += red[tid + o];
        __syncthreads();
    }
    const float v512 = red[0] * 0.03125f;   // / sqrt(1024)
    __syncthreads();

    const int s0 = tid, s1 = tid + 256;
    float x0 = g_att[(size_t)bt * SRC + s0] * 0.03125f;
    float x1 = g_att[(size_t)bt * SRC + s1] * 0.03125f;
    if (mask[b * SRC + s0]) x0 = NEG_BIG;
    if (mask[b * SRC + s1]) x1 = NEG_BIG;

    // max
    red[tid] = fmaxf(fmaxf(x0, x1), v512);
    __syncthreads();
    for (int o = 128; o > 0; o >>= 1) {
        if (tid < o) red[tid] = fmaxf(red[tid], red[tid + o]);
        __syncthreads();
    }
    const float m = red[0];
    __syncthreads();

    // sum exp
    float ls = expf(x0 - m) + expf(x1 - m);
    if (tid == 0) ls += expf(v512 - m);
    red[tid] = ls;
    __syncthreads();
    for (int o = 128; o > 0; o >>= 1) {
        if (tid < o) red[tid] += red[tid + o];
        __syncthreads();
    }
    const float lse = m + logf(red[0]);

    g_pexp[(size_t)bt * SRC + s0] = expf(x0 - lse);
    g_pexp[(size_t)bt * SRC + s1] = expf(x1 - lse);

    if (tid == 0) {
        const float g  = v512 - lse;                 // pointer_gate (log)
        const float eg = expf(g);
        const float c1 = log1pf(-eg + EPSF);         // log1p(-exp(g)+EPS)
        const float c2 = logf(1.0f - eg + EPSF);     // log(1 - exp(g) + EPS)
        const float t2d = (logf(EPSF) - c1) + c2;    // term2 when p == 0
        g_rowc[bt] = make_float4(g, c1, c2, t2d);
    }
}

// ---------------------------------------------------------------------------
// Kernel 4: final fused output per (b,t) row.
//  smem p[20000]: zero -> scatter exp(atten) by content_e -> sweep.
//  out[v<TV]  = logsumexp(logit - lse + g, term2(p[v]))
//  out[v>=TV] = term2(p[v])
// ---------------------------------------------------------------------------
__device__ __forceinline__ float term2f(float pv, float c1, float c2, float t2d) {
    return (pv == 0.f) ? t2d : (logf(pv + EPSF) - c1) + c2;
}
__device__ __forceinline__ float lsexp2(float a, float bb) {
    const float mm = fmaxf(a, bb);
    const float d = fabsf(a - bb);
    return (d > 20.f) ? mm : mm + log1pf(expf(-d));
}

__global__ __launch_bounds__(256) void k_final(
    const float* __restrict__ logits, const int* __restrict__ content,
    float* __restrict__ out)
{
    extern __shared__ __align__(16) float p[];     // VOC floats (80 KB)
    __shared__ float mred[256], sred[256];

    const int bt = blockIdx.x;
    const int b = bt / TGT;
    const int tid = threadIdx.x;
    float4* p4 = (float4*)p;

    for (int i = tid; i < VOC / 4; i += 256) p4[i] = make_float4(0.f, 0.f, 0.f, 0.f);
    __syncthreads();

    for (int s = tid; s < SRC; s += 256)
        atomicAdd(&p[content[b * SRC + s]], g_pexp[(size_t)bt * SRC + s]);

    // streaming logsumexp over logits row (syncthreads below also fences the scatter)
    const float* lrow = logits + (size_t)bt * TV;
    float m = -3.402823466e38f, sm = 0.f;
    for (int i = tid; i < TV / 4; i += 256) {
        const float4 x4 = ((const float4*)lrow)[i];
        const float xs[4] = {x4.x, x4.y, x4.z, x4.w};
#pragma unroll
        for (int j = 0; j < 4; j++) {
            const float x = xs[j];
            if (x > m) { sm *= expf(m - x); m = x; }
            sm += expf(x - m);
        }
    }
    mred[tid] = m; sred[tid] = sm;
    __syncthreads();
    for (int o = 128; o > 0; o >>= 1) {
        if (tid < o) {
            const float m2 = mred[tid + o], s2 = sred[tid + o];
            const float M = fmaxf(mred[tid], m2);
            sred[tid] = sred[tid] * expf(mred[tid] - M) + s2 * expf(m2 - M);
            mred[tid] = M;
        }
        __syncthreads();
    }
    const float lse = mred[0] + logf(sred[0]);

    const float4 rc = g_rowc[bt];
    const float g = rc.x, c1 = rc.y, c2 = rc.z, t2d = rc.w;
    float* orow = out + (size_t)bt * VOC;

    // v < 15000 : merge with vocab log-softmax
    for (int i4 = tid; i4 < TV / 4; i4 += 256) {
        const float4 l4 = ((const float4*)lrow)[i4];
        const float4 pv4 = p4[i4];
        float4 o;
        o.x = lsexp2((l4.x - lse) + g, term2f(pv4.x, c1, c2, t2d));
        o.y = lsexp2((l4.y - lse) + g, term2f(pv4.y, c1, c2, t2d));
        o.z = lsexp2((l4.z - lse) + g, term2f(pv4.z, c1, c2, t2d));
        o.w = lsexp2((l4.w - lse) + g, term2f(pv4.w, c1, c2, t2d));
        ((float4*)orow)[i4] = o;
    }
    // v >= 15000 : out_pad = -inf  ->  result is exactly term2
    for (int i4 = TV / 4 + tid; i4 < VOC / 4; i4 += 256) {
        const float4 pv4 = p4[i4];
        float4 o;
        o.x = term2f(pv4.x, c1, c2, t2d);
        o.y = term2f(pv4.y, c1, c2, t2d);
        o.z = term2f(pv4.z, c1, c2, t2d);
        o.w = term2f(pv4.w, c1, c2, t2d);
        ((float4*)orow)[i4] = o;
    }
}

// ---------------------------------------------------------------------------
extern "C" void kernel_launch(void* const* d_in, const int* in_sizes, int n_in,
                              void* d_out, int out_size)
{
    const float* logits   = (const float*)d_in[0];
    const float* feature  = (const float*)d_in[1];
    const float* memory   = (const float*)d_in[2];
    const float* W_q      = (const float*)d_in[3];
    const float* b_q      = (const float*)d_in[4];
    const float* sentinel = (const float*)d_in[5];
    const unsigned char* mask = (const unsigned char*)d_in[6];
    const int* content    = (const int*)d_in[7];
    float* out = (float*)d_out;

    (void)in_sizes; (void)n_in; (void)out_size;

    k_gemm_gelu<<<dim3(HID / 64, BT / 128), 256>>>(feature, W_q, b_q);
    k_att_gemm<<<dim3(SRC / 64, TGT / 128, BSZ), 256>>>(memory);
    k_softmax_row<<<BT, 256>>>(sentinel, mask);

    cudaFuncSetAttribute(k_final, cudaFuncAttributeMaxDynamicSharedMemorySize, VOC * 4);
    k_final<<<BT, 256, VOC * 4>>>(logits, content, out);
}

// round 2
// speedup vs baseline: 1.1677x; 1.1677x over previous
#include <cuda_runtime.h>
#include <math.h>

// Problem constants (fixed shapes from setup_inputs)
#define BSZ 8
#define SRC 512
#define TGT 256
#define HID 1024
#define TV  15000
#define VOC 20000
#define BT  (BSZ*TGT)   // 2048
#define EPSF 1.1920928955078125e-7f
#define NEG_BIG -1000000000.0f

// Scratch (device globals; no allocations allowed)
__device__ float g_Q[BT * HID];          // gelu(feature @ W_q^T + b_q)   8 MB
__device__ float g_att[BT * SRC];        // raw Q.K^T (pre-scale)          4 MB
__device__ float g_pexp[BT * SRC];       // exp(pointer_atten)             4 MB
__device__ float4 g_rowc[BT];            // {gate, c1, c2, t2default}
__device__ float g_lse[BT];              // logsumexp of logits per row
__device__ int   g_leader[BSZ * SRC];    // first-occurrence index per (b,s)

// ---------------------------------------------------------------------------
// Kernel 1: Q = gelu(feature @ W_q^T + b_q)
// Tile 128(M) x 64(N) x 16(K), 256 threads, 8x4 microtile, double-buffered.
// ---------------------------------------------------------------------------
__global__ __launch_bounds__(256, 2) void k_gemm_gelu(
    const float* __restrict__ A, const float* __restrict__ B,
    const float* __restrict__ bias)
{
    __shared__ __align__(16) float As[2][16][132];
    __shared__ __align__(16) float Bs[2][16][68];

    const int tid = threadIdx.x;
    const int m0 = blockIdx.y * 128;
    const int n0 = blockIdx.x * 64;
    const int tx = tid & 15;
    const int ty = tid >> 4;

    const int am0 = tid >> 2;
    const int am1 = am0 + 64;
    const int ak4 = (tid & 3) * 4;
    const int bn  = tid >> 2;

    const float* Ap0 = A + (size_t)(m0 + am0) * HID + ak4;
    const float* Ap1 = A + (size_t)(m0 + am1) * HID + ak4;
    const float* Bp  = B + (size_t)(n0 + bn)  * HID + ak4;

    float4 ra0 = *(const float4*)Ap0;
    float4 ra1 = *(const float4*)Ap1;
    float4 rb  = *(const float4*)Bp;

#define STORE_TILE_1(bf) do { \
    As[bf][ak4+0][am0]=ra0.x; As[bf][ak4+1][am0]=ra0.y; As[bf][ak4+2][am0]=ra0.z; As[bf][ak4+3][am0]=ra0.w; \
    As[bf][ak4+0][am1]=ra1.x; As[bf][ak4+1][am1]=ra1.y; As[bf][ak4+2][am1]=ra1.z; As[bf][ak4+3][am1]=ra1.w; \
    Bs[bf][ak4+0][bn]=rb.x;   Bs[bf][ak4+1][bn]=rb.y;   Bs[bf][ak4+2][bn]=rb.z;   Bs[bf][ak4+3][bn]=rb.w;   \
    } while(0)

    STORE_TILE_1(0);
    __syncthreads();

    float acc[8][4];
#pragma unroll
    for (int i = 0; i < 8; i++)
#pragma unroll
        for (int j = 0; j < 4; j++) acc[i][j] = 0.f;

    const int NK = HID / 16;
    for (int kc = 0; kc < NK; kc++) {
        const int cur = kc & 1;
        if (kc + 1 < NK) {
            const int ko = (kc + 1) * 16;
            ra0 = *(const float4*)(Ap0 + ko);
            ra1 = *(const float4*)(Ap1 + ko);
            rb  = *(const float4*)(Bp  + ko);
        }
#pragma unroll
        for (int kk = 0; kk < 16; kk++) {
            float4 a0 = *(const float4*)&As[cur][kk][ty * 8];
            float4 a1 = *(const float4*)&As[cur][kk][ty * 8 + 4];
            float4 bb = *(const float4*)&Bs[cur][kk][tx * 4];
            float av[8] = {a0.x,a0.y,a0.z,a0.w,a1.x,a1.y,a1.z,a1.w};
            float bv[4] = {bb.x,bb.y,bb.z,bb.w};
#pragma unroll
            for (int i = 0; i < 8; i++)
#pragma unroll
                for (int j = 0; j < 4; j++)
                    acc[i][j] = fmaf(av[i], bv[j], acc[i][j]);
        }
        if (kc + 1 < NK) {
            STORE_TILE_1(cur ^ 1);
            __syncthreads();
        }
    }

    const float4 b4 = *(const float4*)&bias[n0 + tx * 4];
    const float bvv[4] = {b4.x, b4.y, b4.z, b4.w};
#pragma unroll
    for (int i = 0; i < 8; i++) {
        const int row = m0 + ty * 8 + i;
        float o[4];
#pragma unroll
        for (int j = 0; j < 4; j++) {
            float v = acc[i][j] + bvv[j];
            o[j] = 0.5f * v * (1.0f + erff(v * 0.70710678118654752f));
        }
        *(float4*)&g_Q[(size_t)row * HID + n0 + tx * 4] = make_float4(o[0], o[1], o[2], o[3]);
    }
#undef STORE_TILE_1
}

// ---------------------------------------------------------------------------
// Kernel 2: raw attention GEMM per batch: att[b,t,s] = Q[b,t,:].memory[b,s,:]
// ---------------------------------------------------------------------------
__global__ __launch_bounds__(256, 2) void k_att_gemm(const float* __restrict__ memory)
{
    __shared__ __align__(16) float As[2][16][132];
    __shared__ __align__(16) float Bs[2][16][68];

    const int tid = threadIdx.x;
    const int b  = blockIdx.z;
    const int m0 = blockIdx.y * 128;
    const int n0 = blockIdx.x * 64;
    const int tx = tid & 15;
    const int ty = tid >> 4;

    const int am0 = tid >> 2;
    const int am1 = am0 + 64;
    const int ak4 = (tid & 3) * 4;
    const int bn  = tid >> 2;

    const float* Ap0 = g_Q + (size_t)(b * TGT + m0 + am0) * HID + ak4;
    const float* Ap1 = g_Q + (size_t)(b * TGT + m0 + am1) * HID + ak4;
    const float* Bp  = memory + ((size_t)b * SRC + n0 + bn) * HID + ak4;

    float4 ra0 = *(const float4*)Ap0;
    float4 ra1 = *(const float4*)Ap1;
    float4 rb  = *(const float4*)Bp;

#define STORE_TILE_2(bf) do { \
    As[bf][ak4+0][am0]=ra0.x; As[bf][ak4+1][am0]=ra0.y; As[bf][ak4+2][am0]=ra0.z; As[bf][ak4+3][am0]=ra0.w; \
    As[bf][ak4+0][am1]=ra1.x; As[bf][ak4+1][am1]=ra1.y; As[bf][ak4+2][am1]=ra1.z; As[bf][ak4+3][am1]=ra1.w; \
    Bs[bf][ak4+0][bn]=rb.x;   Bs[bf][ak4+1][bn]=rb.y;   Bs[bf][ak4+2][bn]=rb.z;   Bs[bf][ak4+3][bn]=rb.w;   \
    } while(0)

    STORE_TILE_2(0);
    __syncthreads();

    float acc[8][4];
#pragma unroll
    for (int i = 0; i < 8; i++)
#pragma unroll
        for (int j = 0; j < 4; j++) acc[i][j] = 0.f;

    const int NK = HID / 16;
    for (int kc = 0; kc < NK; kc++) {
        const int cur = kc & 1;
        if (kc + 1 < NK) {
            const int ko = (kc + 1) * 16;
            ra0 = *(const float4*)(Ap0 + ko);
            ra1 = *(const float4*)(Ap1 + ko);
            rb  = *(const float4*)(Bp  + ko);
        }
#pragma unroll
        for (int kk = 0; kk < 16; kk++) {
            float4 a0 = *(const float4*)&As[cur][kk][ty * 8];
            float4 a1 = *(const float4*)&As[cur][kk][ty * 8 + 4];
            float4 bb = *(const float4*)&Bs[cur][kk][tx * 4];
            float av[8] = {a0.x,a0.y,a0.z,a0.w,a1.x,a1.y,a1.z,a1.w};
            float bv[4] = {bb.x,bb.y,bb.z,bb.w};
#pragma unroll
            for (int i = 0; i < 8; i++)
#pragma unroll
                for (int j = 0; j < 4; j++)
                    acc[i][j] = fmaf(av[i], bv[j], acc[i][j]);
        }
        if (kc + 1 < NK) {
            STORE_TILE_2(cur ^ 1);
            __syncthreads();
        }
    }

#pragma unroll
    for (int i = 0; i < 8; i++) {
        const int row = b * TGT + m0 + ty * 8 + i;
        *(float4*)&g_att[(size_t)row * SRC + n0 + tx * 4] =
            make_float4(acc[i][0], acc[i][1], acc[i][2], acc[i][3]);
    }
#undef STORE_TILE_2
}

// ---------------------------------------------------------------------------
// Kernel 3: per-(b,t) row: sentinel dot, mask, log_softmax over 513,
// store exp(pointer_atten) and row constants.
// ---------------------------------------------------------------------------
__global__ __launch_bounds__(256) void k_softmax_row(
    const float* __restrict__ sentinel, const unsigned char* __restrict__ mask)
{
    const int bt = blockIdx.x;
    const int b = bt / TGT;
    const int tid = threadIdx.x;
    __shared__ float red[256];

    {
        const float4 qa = *(const float4*)(g_Q + (size_t)bt * HID + tid * 4);
        const float4 sa = *(const float4*)(sentinel + tid * 4);
        red[tid] = qa.x*sa.x + qa.y*sa.y + qa.z*sa.z + qa.w*sa.w;
    }
    __syncthreads();
    for (int o = 128; o > 0; o >>= 1) {
        if (tid < o) red[tid] += red[tid + o];
        __syncthreads();
    }
    const float v512 = red[0] * 0.03125f;
    __syncthreads();

    const int s0 = tid, s1 = tid + 256;
    float x0 = g_att[(size_t)bt * SRC + s0] * 0.03125f;
    float x1 = g_att[(size_t)bt * SRC + s1] * 0.03125f;
    if (mask[b * SRC + s0]) x0 = NEG_BIG;
    if (mask[b * SRC + s1]) x1 = NEG_BIG;

    red[tid] = fmaxf(fmaxf(x0, x1), v512);
    __syncthreads();
    for (int o = 128; o > 0; o >>= 1) {
        if (tid < o) red[tid] = fmaxf(red[tid], red[tid + o]);
        __syncthreads();
    }
    const float m = red[0];
    __syncthreads();

    float ls = expf(x0 - m) + expf(x1 - m);
    if (tid == 0) ls += expf(v512 - m);
    red[tid] = ls;
    __syncthreads();
    for (int o = 128; o > 0; o >>= 1) {
        if (tid < o) red[tid] += red[tid + o];
        __syncthreads();
    }
    const float lse = m + logf(red[0]);

    g_pexp[(size_t)bt * SRC + s0] = expf(x0 - lse);
    g_pexp[(size_t)bt * SRC + s1] = expf(x1 - lse);

    if (tid == 0) {
        const float g  = v512 - lse;
        const float eg = expf(g);
        const float c1 = log1pf(-eg + EPSF);
        const float c2 = logf(1.0f - eg + EPSF);
        const float t2d = (logf(EPSF) - c1) + c2;
        g_rowc[bt] = make_float4(g, c1, c2, t2d);
    }
}

// ---------------------------------------------------------------------------
// Kernel 4a: per-row streaming logsumexp of logits
// ---------------------------------------------------------------------------
__global__ __launch_bounds__(256) void k_lse(const float* __restrict__ logits)
{
    const int bt = blockIdx.x;
    const int tid = threadIdx.x;
    __shared__ float mred[256], sred[256];

    const float* lrow = logits + (size_t)bt * TV;
    float m = -3.402823466e38f, sm = 0.f;
    for (int i = tid; i < TV / 4; i += 256) {
        const float4 x4 = ((const float4*)lrow)[i];
        const float xs[4] = {x4.x, x4.y, x4.z, x4.w};
#pragma unroll
        for (int j = 0; j < 4; j++) {
            const float x = xs[j];
            if (x > m) { sm *= expf(m - x); m = x; }
            sm += expf(x - m);
        }
    }
    mred[tid] = m; sred[tid] = sm;
    __syncthreads();
    for (int o = 128; o > 0; o >>= 1) {
        if (tid < o) {
            const float m2 = mred[tid + o], s2 = sred[tid + o];
            const float M = fmaxf(mred[tid], m2);
            sred[tid] = sred[tid] * expf(mred[tid] - M) + s2 * expf(m2 - M);
            mred[tid] = M;
        }
        __syncthreads();
    }
    if (tid == 0) g_lse[bt] = mred[0] + logf(sred[0]);
}

// ---------------------------------------------------------------------------
// helpers
// ---------------------------------------------------------------------------
__device__ __forceinline__ float term2f(float pv, float c1, float c2, float t2d) {
    return (pv == 0.f) ? t2d : (logf(pv + EPSF) - c1) + c2;
}
__device__ __forceinline__ float lsexp2(float a, float bb) {
    const float mm = fmaxf(a, bb);
    const float d = fabsf(a - bb);
    return (d > 20.f) ? mm : mm + log1pf(expf(-d));
}

// ---------------------------------------------------------------------------
// Kernel 4b: fully streaming default-path writer (assumes p == 0 everywhere).
// grid: (chunks, BT). VOC/4 = 5000 float4 per row.
// ---------------------------------------------------------------------------
__global__ __launch_bounds__(256) void k_default(
    const float* __restrict__ logits, float* __restrict__ out)
{
    const int bt = blockIdx.y;
    const int i4 = blockIdx.x * 256 + threadIdx.x;
    if (i4 >= VOC / 4) return;

    const float4 rc = g_rowc[bt];
    const float g = rc.x, t2d = rc.w;
    const float lse = g_lse[bt];
    float4 o;

    if (i4 < TV / 4) {
        const float4 l4 = ((const float4*)(logits + (size_t)bt * TV))[i4];
        o.x = lsexp2((l4.x - lse) + g, t2d);
        o.y = lsexp2((l4.y - lse) + g, t2d);
        o.z = lsexp2((l4.z - lse) + g, t2d);
        o.w = lsexp2((l4.w - lse) + g, t2d);
    } else {
        o.x = o.y = o.z = o.w = t2d;   // out_pad = -inf, p = 0  ->  exactly t2d
    }
    ((float4*)(out + (size_t)bt * VOC))[i4] = o;
}

// ---------------------------------------------------------------------------
// Kernel 4c: duplicate resolution per batch: leader[s] = first s' with same id
// ---------------------------------------------------------------------------
__global__ __launch_bounds__(512) void k_leader(const int* __restrict__ content)
{
    const int b = blockIdx.x;
    const int s = threadIdx.x;
    __shared__ int cv[SRC];
    cv[s] = content[b * SRC + s];
    __syncthreads();
    const int v = cv[s];
    int lead = s;
    for (int j = 0; j < SRC; j++) {
        if (cv[j] == v) { lead = j; break; }
    }
    g_leader[b * SRC + s] = lead;
}

// ---------------------------------------------------------------------------
// Kernel 4d: fixup of touched vocab entries. One block per (b,t), 512 threads.
// Compact smem accumulator keyed by leader-s; leaders overwrite out slots.
// ---------------------------------------------------------------------------
__global__ __launch_bounds__(512) void k_fixup(
    const float* __restrict__ logits, const int* __restrict__ content,
    float* __restrict__ out)
{
    const int bt = blockIdx.x;
    const int b = bt / TGT;
    const int s = threadIdx.x;
    __shared__ float ps[SRC];

    ps[s] = 0.f;
    __syncthreads();

    const int lead = g_leader[b * SRC + s];
    atomicAdd(&ps[lead], g_pexp[(size_t)bt * SRC + s]);
    __syncthreads();

    if (lead == s) {
        const int v = content[b * SRC + s];
        const float4 rc = g_rowc[bt];
        const float g = rc.x, c1 = rc.y, c2 = rc.z, t2d = rc.w;
        const float t2 = term2f(ps[s], c1, c2, t2d);
        float o;
        if (v < TV) {
            const float lse = g_lse[bt];
            const float t1 = (logits[(size_t)bt * TV + v] - lse) + g;
            o = lsexp2(t1, t2);
        } else {
            o = t2;
        }
        out[(size_t)bt * VOC + v] = o;
    }
}

// ---------------------------------------------------------------------------
extern "C" void kernel_launch(void* const* d_in, const int* in_sizes, int n_in,
                              void* d_out, int out_size)
{
    const float* logits   = (const float*)d_in[0];
    const float* feature  = (const float*)d_in[1];
    const float* memory   = (const float*)d_in[2];
    const float* W_q      = (const float*)d_in[3];
    const float* b_q      = (const float*)d_in[4];
    const float* sentinel = (const float*)d_in[5];
    const unsigned char* mask = (const unsigned char*)d_in[6];
    const int* content    = (const int*)d_in[7];
    float* out = (float*)d_out;

    (void)in_sizes; (void)n_in; (void)out_size;

    k_gemm_gelu<<<dim3(HID / 64, BT / 128), 256>>>(feature, W_q, b_q);
    k_att_gemm<<<dim3(SRC / 64, TGT / 128, BSZ), 256>>>(memory);
    k_softmax_row<<<BT, 256>>>(sentinel, mask);
    k_lse<<<BT, 256>>>(logits);
    k_leader<<<BSZ, 512>>>(content);
    k_default<<<dim3((VOC / 4 + 255) / 256, BT), 256>>>(logits, out);
    k_fixup<<<BT, 512>>>(logits, content, out);
}